// round 3
// baseline (speedup 1.0000x reference)
#include <cuda_runtime.h>
#include <math.h>

// -------------------------------------------------------------------------
// MultiTaskLoss, fully fused single kernel.
// Block roles: [0,96) det  (image,scale), [96] cls_pred focal,
//              [97, GRID) seg BCE grid-stride.
// Every block writes one pre-weighted float partial; the LAST block to
// finish reduces all partials in double and writes the scalar, then resets
// the arrival counter (graph-replay safe, deterministic).
// -------------------------------------------------------------------------

#define GRID_BLOCKS 1184        // 148 SMs x 8 CTAs -> exactly one wave
#define DET_BLOCKS  96
#define CLS_BID     DET_BLOCKS
#define SEG_BASE    (DET_BLOCKS + 1)
#define SEG_BLOCKS  (GRID_BLOCKS - SEG_BASE)   // 1087

__device__ float g_part[GRID_BLOCKS];
__device__ int   g_counter = 0;

// ---------------- helpers ----------------

__device__ __forceinline__ float bce_logits_f(float x, float y) {
    return fmaxf(x, 0.f) - x * y + __logf(1.f + __expf(-fabsf(x)));
}

__device__ __forceinline__ float block_reduce_f(float v, float* sh) {
    #pragma unroll
    for (int o = 16; o > 0; o >>= 1) v += __shfl_down_sync(0xffffffffu, v, o);
    int lane = threadIdx.x & 31, wid = threadIdx.x >> 5;
    int nw = blockDim.x >> 5;
    if (lane == 0) sh[wid] = v;
    __syncthreads();
    float r = 0.f;
    if (wid == 0) {
        r = (lane < nw) ? sh[lane] : 0.f;
        #pragma unroll
        for (int o = 16; o > 0; o >>= 1) r += __shfl_down_sync(0xffffffffu, r, o);
    }
    __syncthreads();
    return r;
}

__device__ __forceinline__ int block_reduce_i(int v, int* sh) {
    #pragma unroll
    for (int o = 16; o > 0; o >>= 1) v += __shfl_down_sync(0xffffffffu, v, o);
    int lane = threadIdx.x & 31, wid = threadIdx.x >> 5;
    int nw = blockDim.x >> 5;
    if (lane == 0) sh[wid] = v;
    __syncthreads();
    int r = 0;
    if (wid == 0) {
        r = (lane < nw) ? sh[lane] : 0;
        #pragma unroll
        for (int o = 16; o > 0; o >>= 1) r += __shfl_down_sync(0xffffffffu, r, o);
    }
    __syncthreads();
    return r;
}

// ---------------- det role ----------------

__device__ float det_block(int bid,
    const float* __restrict__ cls0, const float* __restrict__ cls1, const float* __restrict__ cls2,
    const float* __restrict__ reg0, const float* __restrict__ reg1, const float* __restrict__ reg2,
    const float* __restrict__ cen0, const float* __restrict__ cen1, const float* __restrict__ cen2,
    const float* __restrict__ boxes, const int* __restrict__ labels,
    float* shf, int* shi) {

    const int s = bid % 3;
    const int b = bid / 3;

    const float* cls; const float* reg; const float* cen;
    int H; float stride;
    if (s == 0)      { cls = cls0; reg = reg0; cen = cen0; H = 64; stride = 8.f;  }
    else if (s == 1) { cls = cls1; reg = reg1; cen = cen1; H = 32; stride = 16.f; }
    else             { cls = cls2; reg = reg2; cen = cen2; H = 16; stride = 32.f; }
    const int W = H;
    const int L = H * W;

    __shared__ float sx0[20], sy0[20], sx1[20], sy1[20], sarea[20];
    __shared__ int   slab[20];

    if (threadIdx.x < 20) {
        int j = threadIdx.x;
        const float* bx = boxes + ((long)b * 20 + j) * 4;
        float cx = bx[0] * 512.f, cy = bx[1] * 512.f;
        float wd = bx[2] * 512.f, ht = bx[3] * 512.f;
        float x0 = cx - wd * 0.5f, y0 = cy - ht * 0.5f;
        float x1 = cx + wd * 0.5f, y1 = cy + ht * 0.5f;
        sx0[j] = x0; sy0[j] = y0; sx1[j] = x1; sy1[j] = y1;
        sarea[j] = (x1 - x0) * (y1 - y0);
        slab[j]  = labels[(long)b * 20 + j];
    }
    __syncthreads();

    const float inv_stride = 1.f / stride;
    float cls_sum = 0.f, reg_sum = 0.f, cen_sum = 0.f;
    int npos = 0;

    for (int loc = threadIdx.x; loc < L; loc += blockDim.x) {
        int h = loc / W;
        int w = loc - h * W;
        float lx = ((float)w + 0.5f) * stride;
        float ly = ((float)h + 0.5f) * stride;

        // argmin over inside boxes (first-minimum tie-break = jnp.argmin)
        int   bj = -1;
        float barea = INFINITY;
        #pragma unroll
        for (int j = 0; j < 20; j++) {
            float l  = lx - sx0[j];
            float t  = ly - sy0[j];
            float r  = sx1[j] - lx;
            float bt = sy1[j] - ly;
            float mn = fminf(fminf(l, t), fminf(r, bt));
            if (mn > 0.f && sarea[j] < barea) { barea = sarea[j]; bj = j; }
        }
        int ct = (bj >= 0) ? slab[bj] : -1;

        // focal over 4 classes (channels 1..4 of 5-channel logits)
        const float* clsb = cls + ((long)b * 5 + 1) * L + loc;
        #pragma unroll
        for (int c = 0; c < 4; c++) {
            float x = clsb[(long)c * L];
            float t = (c == ct) ? 1.f : 0.f;
            float e = __expf(-fabsf(x));
            float inv1e = 1.f / (1.f + e);
            float p = (x >= 0.f) ? inv1e : e * inv1e;
            float ce = fmaxf(x, 0.f) - x * t + __logf(1.f + e);
            float pt = p * t + (1.f - p) * (1.f - t);
            float at = 0.25f * t + 0.75f * (1.f - t);
            float u = 1.f - pt;
            cls_sum += at * u * u * ce;
        }

        if (bj >= 0) {
            npos++;
            float rt0 = (lx - sx0[bj]) * inv_stride;
            float rt1 = (ly - sy0[bj]) * inv_stride;
            float rt2 = (sx1[bj] - lx) * inv_stride;
            float rt3 = (sy1[bj] - ly) * inv_stride;

            const float* rb = reg + (long)b * 4 * L + loc;
            float rt[4] = { rt0, rt1, rt2, rt3 };
            float sl = 0.f;
            #pragma unroll
            for (int k = 0; k < 4; k++) {
                float d  = rb[(long)k * L] - rt[k];
                float ad = fabsf(d);
                sl += (ad < 1.f) ? 0.5f * d * d : (ad - 0.5f);
            }
            reg_sum += sl * 0.25f;

            const float eps = 1e-6f;
            float mnlr = fminf(rt0, rt2), mxlr = fmaxf(rt0, rt2);
            float mntb = fminf(rt1, rt3), mxtb = fmaxf(rt1, rt3);
            float c2 = (mnlr / (mxlr + eps)) * (mntb / (mxtb + eps));
            c2 = fminf(fmaxf(c2, 0.f), 1.f);
            float cent_t = sqrtf(c2);
            float cx = cen[(long)b * L + loc];
            cen_sum += bce_logits_f(cx, cent_t);
        }
    }

    float cls_tot = block_reduce_f(cls_sum, shf);
    float reg_tot = block_reduce_f(reg_sum, shf);
    float cen_tot = block_reduce_f(cen_sum, shf);
    int   np_tot  = block_reduce_i(npos, shi);

    float cls_l = cls_tot / (float)(L * 4);
    float reg_l = (np_tot > 0) ? reg_tot / (float)np_tot : 0.f;
    float cen_l = (np_tot > 0) ? cen_tot / (float)np_tot : 0.f;
    return (cls_l + reg_l + cen_l) * (1.f / 96.f);   // /(3 scales * 32 images)
}

// ---------------- clspred role ----------------

__device__ float cls_block(const float* __restrict__ pred,
                           const int*   __restrict__ target, float* sh) {
    float acc = 0.f;
    for (int i = threadIdx.x; i < 320; i += blockDim.x) {
        int bb = i / 10;
        int c  = i - bb * 10;
        float x = pred[i];
        float t = (target[bb] == c) ? 1.f : 0.f;
        float e = __expf(-fabsf(x));
        float inv1e = 1.f / (1.f + e);
        float p = (x >= 0.f) ? inv1e : e * inv1e;
        float ce = fmaxf(x, 0.f) - x * t + __logf(1.f + e);
        float pt = p * t + (1.f - p) * (1.f - t);
        float at = 0.25f * t + 0.75f * (1.f - t);
        float u = 1.f - pt;
        acc += at * u * u * ce;
    }
    float tot = block_reduce_f(acc, sh);
    return tot * (0.5f / 320.f);   // W_CLS * mean
}

// ---------------- seg role ----------------

__device__ float seg_block(int sbid,
                           const float* __restrict__ logits,
                           const int*   __restrict__ mask, float* sh) {
    const int NV = 32 * 65536;              // total float4 groups per mask

    float acc = 0.f;
    for (int v = sbid * blockDim.x + threadIdx.x; v < NV;
         v += SEG_BLOCKS * blockDim.x) {
        int b = v >> 16;
        int r = v & 0xFFFF;
        int4 m4 = __ldcs(reinterpret_cast<const int4*>(mask) + ((long)b << 16) + r);
        float y0 = (float)m4.x, y1 = (float)m4.y, y2 = (float)m4.z, y3 = (float)m4.w;
        long base = ((long)b << 18) + r;    // b*4*HW4 + r
        #pragma unroll
        for (int c = 0; c < 4; c++) {
            float4 x = __ldcs(reinterpret_cast<const float4*>(logits) + base + ((long)c << 16));
            acc += bce_logits_f(x.x, y0);
            acc += bce_logits_f(x.y, y1);
            acc += bce_logits_f(x.z, y2);
            acc += bce_logits_f(x.w, y3);
        }
    }
    float tot = block_reduce_f(acc, sh);
    return tot * (1.f / 33554432.f);        // mean over 32*4*512*512
}

// ---------------- fused kernel with tail reduction ----------------

__global__ void __launch_bounds__(256) fused_kernel(
    const float* __restrict__ seg_logits, const int* __restrict__ seg_mask,
    const float* __restrict__ cls0, const float* __restrict__ cls1, const float* __restrict__ cls2,
    const float* __restrict__ reg0, const float* __restrict__ reg1, const float* __restrict__ reg2,
    const float* __restrict__ cen0, const float* __restrict__ cen1, const float* __restrict__ cen2,
    const float* __restrict__ boxes, const int* __restrict__ labels,
    const float* __restrict__ cls_pred, const int* __restrict__ cls_target,
    float* __restrict__ out) {

    __shared__ float shf[8];
    __shared__ int   shi[8];
    __shared__ bool  s_last;

    const int bid = blockIdx.x;
    float part;
    if (bid < DET_BLOCKS) {
        part = det_block(bid, cls0, cls1, cls2, reg0, reg1, reg2,
                         cen0, cen1, cen2, boxes, labels, shf, shi);
    } else if (bid == CLS_BID) {
        part = cls_block(cls_pred, cls_target, shf);
    } else {
        part = seg_block(bid - SEG_BASE, seg_logits, seg_mask, shf);
    }

    if (threadIdx.x == 0) {
        g_part[bid] = part;
        __threadfence();
        int arrived = atomicAdd(&g_counter, 1);
        s_last = (arrived == GRID_BLOCKS - 1);
    }
    __syncthreads();

    if (s_last) {
        // last block: reduce all partials in double (deterministic layout)
        __shared__ double shd[8];
        double acc = 0.0;
        for (int i = threadIdx.x; i < GRID_BLOCKS; i += blockDim.x)
            acc += (double)g_part[i];
        #pragma unroll
        for (int o = 16; o > 0; o >>= 1) acc += __shfl_down_sync(0xffffffffu, acc, o);
        int lane = threadIdx.x & 31, wid = threadIdx.x >> 5;
        if (lane == 0) shd[wid] = acc;
        __syncthreads();
        if (wid == 0) {
            double r = (lane < 8) ? shd[lane] : 0.0;
            #pragma unroll
            for (int o = 4; o > 0; o >>= 1) r += __shfl_down_sync(0xffffffffu, r, o);
            if (lane == 0) {
                out[0] = (float)r;
                g_counter = 0;          // reset for next graph replay
            }
        }
    }
}

// ---------------- launch ----------------

extern "C" void kernel_launch(void* const* d_in, const int* in_sizes, int n_in,
                              void* d_out, int out_size) {
    const float* seg_logits = (const float*)d_in[0];
    const int*   seg_mask   = (const int*)  d_in[1];
    const float* cls_s0     = (const float*)d_in[2];
    const float* cls_s1     = (const float*)d_in[3];
    const float* cls_s2     = (const float*)d_in[4];
    const float* reg_s0     = (const float*)d_in[5];
    const float* reg_s1     = (const float*)d_in[6];
    const float* reg_s2     = (const float*)d_in[7];
    const float* cen_s0     = (const float*)d_in[8];
    const float* cen_s1     = (const float*)d_in[9];
    const float* cen_s2     = (const float*)d_in[10];
    const float* boxes      = (const float*)d_in[11];
    const int*   labels     = (const int*)  d_in[12];
    const float* cls_pred   = (const float*)d_in[13];
    const int*   cls_target = (const int*)  d_in[14];
    float* out = (float*)d_out;

    fused_kernel<<<GRID_BLOCKS, 256>>>(
        seg_logits, seg_mask,
        cls_s0, cls_s1, cls_s2,
        reg_s0, reg_s1, reg_s2,
        cen_s0, cen_s1, cen_s2,
        boxes, labels, cls_pred, cls_target, out);
}

// round 5
// speedup vs baseline: 1.2468x; 1.2468x over previous
#include <cuda_runtime.h>
#include <math.h>

// -------------------------------------------------------------------------
// MultiTaskLoss, two kernels with separate register domains:
//  K1: det (96 blocks) + cls_pred (1 block) -> writes weighted partials.
//  K2: seg BCE, 32-reg / full-occupancy; its LAST block reduces ALL
//      partials (its own + K1's, visible via stream order) and writes out.
// -------------------------------------------------------------------------

#define DET_BLOCKS  96
#define K1_BLOCKS   (DET_BLOCKS + 1)
#define SEG_BLOCKS  2048

__device__ float g_part_k1[K1_BLOCKS];
__device__ float g_part_seg[SEG_BLOCKS];
__device__ int   g_counter = 0;

// ---------------- helpers ----------------

__device__ __forceinline__ float bce_logits_f(float x, float y) {
    return fmaxf(x, 0.f) - x * y + __logf(1.f + __expf(-fabsf(x)));
}

__device__ __forceinline__ float block_reduce_f(float v, float* sh) {
    #pragma unroll
    for (int o = 16; o > 0; o >>= 1) v += __shfl_down_sync(0xffffffffu, v, o);
    int lane = threadIdx.x & 31, wid = threadIdx.x >> 5;
    int nw = blockDim.x >> 5;
    if (lane == 0) sh[wid] = v;
    __syncthreads();
    float r = 0.f;
    if (wid == 0) {
        r = (lane < nw) ? sh[lane] : 0.f;
        #pragma unroll
        for (int o = 16; o > 0; o >>= 1) r += __shfl_down_sync(0xffffffffu, r, o);
    }
    __syncthreads();
    return r;
}

__device__ __forceinline__ int block_reduce_i(int v, int* sh) {
    #pragma unroll
    for (int o = 16; o > 0; o >>= 1) v += __shfl_down_sync(0xffffffffu, v, o);
    int lane = threadIdx.x & 31, wid = threadIdx.x >> 5;
    int nw = blockDim.x >> 5;
    if (lane == 0) sh[wid] = v;
    __syncthreads();
    int r = 0;
    if (wid == 0) {
        r = (lane < nw) ? sh[lane] : 0;
        #pragma unroll
        for (int o = 16; o > 0; o >>= 1) r += __shfl_down_sync(0xffffffffu, r, o);
    }
    __syncthreads();
    return r;
}

// ================= K1: det + cls_pred =================

__global__ void __launch_bounds__(256) det_kernel(
    const float* __restrict__ cls0, const float* __restrict__ cls1, const float* __restrict__ cls2,
    const float* __restrict__ reg0, const float* __restrict__ reg1, const float* __restrict__ reg2,
    const float* __restrict__ cen0, const float* __restrict__ cen1, const float* __restrict__ cen2,
    const float* __restrict__ boxes, const int* __restrict__ labels,
    const float* __restrict__ cls_pred, const int* __restrict__ cls_target) {

    __shared__ float shf[8];
    __shared__ int   shi[8];
    const int bid = blockIdx.x;

    if (bid == DET_BLOCKS) {
        // ---- cls_pred focal: (32,10) ----
        float acc = 0.f;
        for (int i = threadIdx.x; i < 320; i += blockDim.x) {
            int bb = i / 10;
            int c  = i - bb * 10;
            float x = cls_pred[i];
            float t = (cls_target[bb] == c) ? 1.f : 0.f;
            float e = __expf(-fabsf(x));
            float inv1e = 1.f / (1.f + e);
            float p = (x >= 0.f) ? inv1e : e * inv1e;
            float ce = fmaxf(x, 0.f) - x * t + __logf(1.f + e);
            float pt = p * t + (1.f - p) * (1.f - t);
            float at = 0.25f * t + 0.75f * (1.f - t);
            float u = 1.f - pt;
            acc += at * u * u * ce;
        }
        float tot = block_reduce_f(acc, shf);
        if (threadIdx.x == 0) g_part_k1[bid] = tot * (0.5f / 320.f);
        return;
    }

    // ---- det: one block per (image, scale) ----
    const int s = bid % 3;
    const int b = bid / 3;

    const float* cls; const float* reg; const float* cen;
    int H; float stride;
    if (s == 0)      { cls = cls0; reg = reg0; cen = cen0; H = 64; stride = 8.f;  }
    else if (s == 1) { cls = cls1; reg = reg1; cen = cen1; H = 32; stride = 16.f; }
    else             { cls = cls2; reg = reg2; cen = cen2; H = 16; stride = 32.f; }
    const int W = H;
    const int L = H * W;

    __shared__ float sx0[20], sy0[20], sx1[20], sy1[20], sarea[20];
    __shared__ int   slab[20];

    if (threadIdx.x < 20) {
        int j = threadIdx.x;
        const float* bx = boxes + ((long)b * 20 + j) * 4;
        float cx = bx[0] * 512.f, cy = bx[1] * 512.f;
        float wd = bx[2] * 512.f, ht = bx[3] * 512.f;
        float x0 = cx - wd * 0.5f, y0 = cy - ht * 0.5f;
        float x1 = cx + wd * 0.5f, y1 = cy + ht * 0.5f;
        sx0[j] = x0; sy0[j] = y0; sx1[j] = x1; sy1[j] = y1;
        sarea[j] = (x1 - x0) * (y1 - y0);
        slab[j]  = labels[(long)b * 20 + j];
    }
    __syncthreads();

    const float inv_stride = 1.f / stride;
    float cls_sum = 0.f, reg_sum = 0.f, cen_sum = 0.f;
    int npos = 0;

    for (int loc = threadIdx.x; loc < L; loc += blockDim.x) {
        int h = loc / W;
        int w = loc - h * W;
        float lx = ((float)w + 0.5f) * stride;
        float ly = ((float)h + 0.5f) * stride;

        // argmin over inside boxes (first-minimum tie-break = jnp.argmin)
        int   bj = -1;
        float barea = INFINITY;
        #pragma unroll
        for (int j = 0; j < 20; j++) {
            float l  = lx - sx0[j];
            float t  = ly - sy0[j];
            float r  = sx1[j] - lx;
            float bt = sy1[j] - ly;
            float mn = fminf(fminf(l, t), fminf(r, bt));
            if (mn > 0.f && sarea[j] < barea) { barea = sarea[j]; bj = j; }
        }
        int ct = (bj >= 0) ? slab[bj] : -1;

        // focal over 4 classes (channels 1..4 of 5-channel logits)
        const float* clsb = cls + ((long)b * 5 + 1) * L + loc;
        #pragma unroll
        for (int c = 0; c < 4; c++) {
            float x = clsb[(long)c * L];
            float t = (c == ct) ? 1.f : 0.f;
            float e = __expf(-fabsf(x));
            float inv1e = 1.f / (1.f + e);
            float p = (x >= 0.f) ? inv1e : e * inv1e;
            float ce = fmaxf(x, 0.f) - x * t + __logf(1.f + e);
            float pt = p * t + (1.f - p) * (1.f - t);
            float at = 0.25f * t + 0.75f * (1.f - t);
            float u = 1.f - pt;
            cls_sum += at * u * u * ce;
        }

        if (bj >= 0) {
            npos++;
            float rt0 = (lx - sx0[bj]) * inv_stride;
            float rt1 = (ly - sy0[bj]) * inv_stride;
            float rt2 = (sx1[bj] - lx) * inv_stride;
            float rt3 = (sy1[bj] - ly) * inv_stride;

            const float* rb = reg + (long)b * 4 * L + loc;
            float rt[4] = { rt0, rt1, rt2, rt3 };
            float sl = 0.f;
            #pragma unroll
            for (int k = 0; k < 4; k++) {
                float d  = rb[(long)k * L] - rt[k];
                float ad = fabsf(d);
                sl += (ad < 1.f) ? 0.5f * d * d : (ad - 0.5f);
            }
            reg_sum += sl * 0.25f;

            const float eps = 1e-6f;
            float mnlr = fminf(rt0, rt2), mxlr = fmaxf(rt0, rt2);
            float mntb = fminf(rt1, rt3), mxtb = fmaxf(rt1, rt3);
            float c2 = (mnlr / (mxlr + eps)) * (mntb / (mxtb + eps));
            c2 = fminf(fmaxf(c2, 0.f), 1.f);
            float cent_t = sqrtf(c2);
            float cx = cen[(long)b * L + loc];
            cen_sum += bce_logits_f(cx, cent_t);
        }
    }

    float cls_tot = block_reduce_f(cls_sum, shf);
    float reg_tot = block_reduce_f(reg_sum, shf);
    float cen_tot = block_reduce_f(cen_sum, shf);
    int   np_tot  = block_reduce_i(npos, shi);

    if (threadIdx.x == 0) {
        float cls_l = cls_tot / (float)(L * 4);
        float reg_l = (np_tot > 0) ? reg_tot / (float)np_tot : 0.f;
        float cen_l = (np_tot > 0) ? cen_tot / (float)np_tot : 0.f;
        g_part_k1[bid] = (cls_l + reg_l + cen_l) * (1.f / 96.f);
    }
}

// ================= K2: seg BCE + tail combine =================
// __launch_bounds__(256, 8) caps regs at 32 -> full occupancy for the
// memory-bound stream.

__global__ void __launch_bounds__(256, 8) seg_kernel(
    const float* __restrict__ logits, const int* __restrict__ mask,
    float* __restrict__ out) {

    const int NV = 32 * 65536;              // total float4 groups of mask
    __shared__ float sh[8];
    __shared__ bool  s_last;

    float acc = 0.f;
    for (int v = blockIdx.x * blockDim.x + threadIdx.x; v < NV;
         v += SEG_BLOCKS * blockDim.x) {
        int b = v >> 16;
        int r = v & 0xFFFF;
        int4 m4 = __ldcs(reinterpret_cast<const int4*>(mask) + ((long)b << 16) + r);
        float y0 = (float)m4.x, y1 = (float)m4.y, y2 = (float)m4.z, y3 = (float)m4.w;
        long base = ((long)b << 18) + r;    // b*4*HW4 + r
        #pragma unroll
        for (int c = 0; c < 4; c++) {
            float4 x = __ldcs(reinterpret_cast<const float4*>(logits) + base + ((long)c << 16));
            acc += bce_logits_f(x.x, y0);
            acc += bce_logits_f(x.y, y1);
            acc += bce_logits_f(x.z, y2);
            acc += bce_logits_f(x.w, y3);
        }
    }
    float tot = block_reduce_f(acc, sh);

    if (threadIdx.x == 0) {
        g_part_seg[blockIdx.x] = tot * (1.f / 33554432.f);   // seg mean weight
        __threadfence();
        int arrived = atomicAdd(&g_counter, 1);
        s_last = (arrived == SEG_BLOCKS - 1);
    }
    __syncthreads();

    if (s_last) {
        __shared__ double shd[8];
        double dacc = 0.0;
        for (int i = threadIdx.x; i < SEG_BLOCKS; i += blockDim.x)
            dacc += (double)g_part_seg[i];
        if (threadIdx.x < K1_BLOCKS)
            dacc += (double)g_part_k1[threadIdx.x];          // det+cls (K1, ordered)
        #pragma unroll
        for (int o = 16; o > 0; o >>= 1) dacc += __shfl_down_sync(0xffffffffu, dacc, o);
        int lane = threadIdx.x & 31, wid = threadIdx.x >> 5;
        if (lane == 0) shd[wid] = dacc;
        __syncthreads();
        if (wid == 0) {
            double r = (lane < 8) ? shd[lane] : 0.0;
            #pragma unroll
            for (int o = 4; o > 0; o >>= 1) r += __shfl_down_sync(0xffffffffu, r, o);
            if (lane == 0) {
                out[0] = (float)r;
                g_counter = 0;          // reset for next graph replay
            }
        }
    }
}

// ---------------- launch ----------------

extern "C" void kernel_launch(void* const* d_in, const int* in_sizes, int n_in,
                              void* d_out, int out_size) {
    const float* seg_logits = (const float*)d_in[0];
    const int*   seg_mask   = (const int*)  d_in[1];
    const float* cls_s0     = (const float*)d_in[2];
    const float* cls_s1     = (const float*)d_in[3];
    const float* cls_s2     = (const float*)d_in[4];
    const float* reg_s0     = (const float*)d_in[5];
    const float* reg_s1     = (const float*)d_in[6];
    const float* reg_s2     = (const float*)d_in[7];
    const float* cen_s0     = (const float*)d_in[8];
    const float* cen_s1     = (const float*)d_in[9];
    const float* cen_s2     = (const float*)d_in[10];
    const float* boxes      = (const float*)d_in[11];
    const int*   labels     = (const int*)  d_in[12];
    const float* cls_pred   = (const float*)d_in[13];
    const int*   cls_target = (const int*)  d_in[14];
    float* out = (float*)d_out;

    det_kernel<<<K1_BLOCKS, 256>>>(
        cls_s0, cls_s1, cls_s2,
        reg_s0, reg_s1, reg_s2,
        cen_s0, cen_s1, cen_s2,
        boxes, labels, cls_pred, cls_target);

    seg_kernel<<<SEG_BLOCKS, 256>>>(seg_logits, seg_mask, out);
}